// round 9
// baseline (speedup 1.0000x reference)
#include <cuda_runtime.h>
#include <cuda_bf16.h>
#include <cstdint>

#define D            128
#define S            16
#define BMAX         8192

// ---------------- scratch (device globals: allocation-free) ----------------
__device__ uint32_t g_x0 [BMAX * D];   // msg + rep0, tf32 bits (GEMM A input)
__device__ float    g_msg[BMAX * D];   // msg fp32 (residual adds)

__device__ __forceinline__ uint32_t f2tf32(float f) {
    uint32_t r;
    asm("cvt.rna.tf32.f32 %0, %1;" : "=r"(r) : "f"(f));
    return r;
}

// ============================ kernel 1: gather =============================
// One warp per item. No smem. 32 warps/SM -> deep gather MLP (measured ~7.5TB/s).
__global__ __launch_bounds__(256, 4)
void gather_kernel(const int* __restrict__ u,
                   const int* __restrict__ v,
                   const int* __restrict__ adj_ent,
                   const int* __restrict__ adj_rel,
                   const float* __restrict__ usr,
                   const float* __restrict__ ent,
                   const float* __restrict__ rel,
                   int B)
{
    const int lane = threadIdx.x & 31;
    const int item = blockIdx.x * 8 + (threadIdx.x >> 5);
    if (item >= B) return;

    const float4* usr4 = (const float4*)usr;
    const float4* ent4 = (const float4*)ent;
    const float4* rel4 = (const float4*)rel;
    const int4*   adjE4 = (const int4*)adj_ent;
    const int4*   adjR4 = (const int4*)adj_rel;

    const int iu = u[item];
    const int iv = v[item];

    const float4 uex = usr4[(size_t)iu * 32 + lane];
    const float4 rp  = ent4[(size_t)iv * 32 + lane];

    int eix[S], rix[S];
    #pragma unroll
    for (int q = 0; q < 4; q++) {
        const int4 e = __ldg(&adjE4[iv * 4 + q]);
        const int4 r = __ldg(&adjR4[iv * 4 + q]);
        eix[q*4+0] = e.x; eix[q*4+1] = e.y; eix[q*4+2] = e.z; eix[q*4+3] = e.w;
        rix[q*4+0] = r.x; rix[q*4+1] = r.y; rix[q*4+2] = r.z; rix[q*4+3] = r.w;
    }

    // fused single-pass attention (scores tiny; no-max-sub exp validated)
    float sum = 0.f;
    float4 msg = make_float4(0.f, 0.f, 0.f, 0.f);
    #pragma unroll
    for (int s = 0; s < S; s++) {
        const float4 r4 = rel4[(size_t)rix[s] * 32 + lane];
        const float4 e4 = ent4[(size_t)eix[s] * 32 + lane];
        float p = uex.x * r4.x + uex.y * r4.y + uex.z * r4.z + uex.w * r4.w;
        #pragma unroll
        for (int o = 16; o > 0; o >>= 1)
            p += __shfl_xor_sync(0xffffffffu, p, o);
        const float es = __expf(p);
        sum += es;
        msg.x = fmaf(es, e4.x, msg.x);
        msg.y = fmaf(es, e4.y, msg.y);
        msg.z = fmaf(es, e4.z, msg.z);
        msg.w = fmaf(es, e4.w, msg.w);
    }
    const float inv = __frcp_rn(sum);
    msg.x *= inv; msg.y *= inv; msg.z *= inv; msg.w *= inv;

    ((float4*)(g_msg + item * D))[lane] = msg;
    ((uint4*)(g_x0 + item * D))[lane] =
        make_uint4(f2tf32(msg.x + rp.x), f2tf32(msg.y + rp.y),
                   f2tf32(msg.z + rp.z), f2tf32(msg.w + rp.w));
}

// ============================ kernel 2: GEMM v2 ============================
// M_BLK=64 per block, grid=128 -> ONE wave. Warp tile M=64 x N=16.
#define MBLK         64
#define GTHREADS     256
#define WSTRIDE      136
#define XSTRIDE      132
#define W_WORDS      (D * WSTRIDE)        // 17408
#define X_WORDS      (MBLK * XSTRIDE)     // 8448
#define SMEM_BYTES   ((W_WORDS + 2 * X_WORDS) * 4)   // 137216 B -> 1 block/SM

__device__ __forceinline__ void mma_tf32(float acc[4], const uint32_t a[4],
                                         const uint32_t b[2]) {
    asm("mma.sync.aligned.m16n8k8.row.col.f32.tf32.tf32.f32 "
        "{%0,%1,%2,%3}, {%4,%5,%6,%7}, {%8,%9}, {%0,%1,%2,%3};"
        : "+f"(acc[0]), "+f"(acc[1]), "+f"(acc[2]), "+f"(acc[3])
        : "r"(a[0]), "r"(a[1]), "r"(a[2]), "r"(a[3]),
          "r"(b[0]), "r"(b[1]));
}

__global__ __launch_bounds__(GTHREADS, 1)
void gemm_kernel(const int* __restrict__ u,
                 const float* __restrict__ usr,
                 const float* __restrict__ W,
                 const float* __restrict__ bias,
                 float* __restrict__ out,
                 int B)
{
    extern __shared__ char smraw[];
    uint32_t* Wsh = (uint32_t*)smraw;                              // tf32 W [128][136]
    uint32_t* Xsh = (uint32_t*)(smraw + W_WORDS * 4);              // tf32 X [64][132]
    float*    Msh = (float*)   (smraw + (W_WORDS + X_WORDS) * 4);  // msg fp32 [64][132]
    float*    Hsh = Msh;                                           // reused: relu(h2)

    const int tid  = threadIdx.x;
    const int lane = tid & 31;
    const int wid  = tid >> 5;
    const int g    = lane >> 2;
    const int tq   = lane & 3;

    // ---- stage W -> shared (tf32, padded stride) ----
    {
        const float4* Wg4 = (const float4*)W;
        #pragma unroll
        for (int k = 0; k < (D * D / 4) / GTHREADS; k++) {
            const int i = tid + k * GTHREADS;
            const float4 w = Wg4[i];
            const int row = (i * 4) >> 7;
            const int col = (i * 4) & 127;
            uint32_t* p = Wsh + row * WSTRIDE + col;
            p[0] = f2tf32(w.x); p[1] = f2tf32(w.y);
            p[2] = f2tf32(w.z); p[3] = f2tf32(w.w);
        }
    }

    // ---- stage X (already tf32) and msg from scratch, coalesced ----
    {
        const int base = blockIdx.x * MBLK;
        #pragma unroll
        for (int r = 0; r < MBLK / 8; r++) {      // 8 rows per warp
            const int row  = wid * (MBLK / 8) + r;
            const int cit  = min(base + row, B - 1);
            ((uint4*)(Xsh + row * XSTRIDE))[lane]  = ((const uint4*)(g_x0  + cit * D))[lane];
            ((float4*)(Msh + row * XSTRIDE))[lane] = ((const float4*)(g_msg + cit * D))[lane];
        }
    }
    __syncthreads();

    // ---- block GEMM: M=64, N=128, K=128; warp owns 16 N-cols, all 64 rows ----
    const int ncol0 = wid * 16;
    float bb[2][2];
    #pragma unroll
    for (int nt = 0; nt < 2; nt++) {
        bb[nt][0] = __ldg(&bias[ncol0 + nt * 8 + tq * 2]);
        bb[nt][1] = __ldg(&bias[ncol0 + nt * 8 + tq * 2 + 1]);
    }

    float acc[4][2][4];   // [mt][nt][frag]

    #pragma unroll
    for (int iter = 0; iter < 2; iter++) {
        #pragma unroll
        for (int mt = 0; mt < 4; mt++)
            #pragma unroll
            for (int nt = 0; nt < 2; nt++) {
                acc[mt][nt][0] = bb[nt][0]; acc[mt][nt][1] = bb[nt][1];
                acc[mt][nt][2] = bb[nt][0]; acc[mt][nt][3] = bb[nt][1];
            }

        #pragma unroll 4
        for (int kt = 0; kt < 16; kt++) {
            uint32_t b[2][2];
            #pragma unroll
            for (int nt = 0; nt < 2; nt++) {
                const uint32_t* wb = Wsh + (kt * 8 + tq) * WSTRIDE + ncol0 + nt * 8 + g;
                b[nt][0] = wb[0];
                b[nt][1] = wb[4 * WSTRIDE];
            }
            #pragma unroll
            for (int mt = 0; mt < 4; mt++) {
                uint32_t a[4];
                const uint32_t* xb = Xsh + (mt * 16 + g) * XSTRIDE + kt * 8 + tq;
                a[0] = xb[0];
                a[1] = xb[8 * XSTRIDE];
                a[2] = xb[4];
                a[3] = xb[8 * XSTRIDE + 4];
                mma_tf32(acc[mt][0], a, b[0]);
                mma_tf32(acc[mt][1], a, b[1]);
            }
        }

        __syncthreads();   // all A reads of Xsh done

        if (iter == 0) {
            // x1 = msg + relu(h1)  (warp writes its own 16 columns)
            #pragma unroll
            for (int mt = 0; mt < 4; mt++) {
                #pragma unroll
                for (int nt = 0; nt < 2; nt++) {
                    const int c0 = ncol0 + nt * 8 + tq * 2;
                    const int r0 = mt * 16 + g;
                    const int r1 = r0 + 8;
                    Xsh[r0 * XSTRIDE + c0    ] = f2tf32(Msh[r0 * XSTRIDE + c0    ] + fmaxf(acc[mt][nt][0], 0.f));
                    Xsh[r0 * XSTRIDE + c0 + 1] = f2tf32(Msh[r0 * XSTRIDE + c0 + 1] + fmaxf(acc[mt][nt][1], 0.f));
                    Xsh[r1 * XSTRIDE + c0    ] = f2tf32(Msh[r1 * XSTRIDE + c0    ] + fmaxf(acc[mt][nt][2], 0.f));
                    Xsh[r1 * XSTRIDE + c0 + 1] = f2tf32(Msh[r1 * XSTRIDE + c0 + 1] + fmaxf(acc[mt][nt][3], 0.f));
                }
            }
            __syncthreads();
        }
    }

    // rep2 = relu(h2) -> Hsh (fp32, overwrites msg: safe after layer 1)
    #pragma unroll
    for (int mt = 0; mt < 4; mt++) {
        #pragma unroll
        for (int nt = 0; nt < 2; nt++) {
            const int c0 = ncol0 + nt * 8 + tq * 2;
            const int r0 = mt * 16 + g;
            const int r1 = r0 + 8;
            Hsh[r0 * XSTRIDE + c0    ] = fmaxf(acc[mt][nt][0], 0.f);
            Hsh[r0 * XSTRIDE + c0 + 1] = fmaxf(acc[mt][nt][1], 0.f);
            Hsh[r1 * XSTRIDE + c0    ] = fmaxf(acc[mt][nt][2], 0.f);
            Hsh[r1 * XSTRIDE + c0 + 1] = fmaxf(acc[mt][nt][3], 0.f);
        }
    }
    __syncthreads();

    // ---- epilogue: sigmoid(dot(u_emb, rep2)); warp handles 8 items ----
    const float4* usr4 = (const float4*)usr;
    const int base = blockIdx.x * MBLK;
    #pragma unroll
    for (int r = 0; r < MBLK / 8; r++) {
        const int row  = wid * (MBLK / 8) + r;
        const int item = base + row;
        const int cit  = min(item, B - 1);
        const int iu = u[cit];
        const float4 uex = usr4[(size_t)iu * 32 + lane];
        const float4 h = ((const float4*)(Hsh + row * XSTRIDE))[lane];
        float p = uex.x * h.x + uex.y * h.y + uex.z * h.z + uex.w * h.w;
        #pragma unroll
        for (int o = 16; o > 0; o >>= 1)
            p += __shfl_xor_sync(0xffffffffu, p, o);
        if (lane == 0 && item < B)
            out[item] = 1.f / (1.f + __expf(-p));
    }
}

// ================================ launch ===================================
extern "C" void kernel_launch(void* const* d_in, const int* in_sizes, int n_in,
                              void* d_out, int out_size)
{
    const int*   u       = (const int*)d_in[0];
    const int*   v       = (const int*)d_in[1];
    const int*   adj_ent = (const int*)d_in[2];
    const int*   adj_rel = (const int*)d_in[3];
    const float* usr     = (const float*)d_in[4];
    const float* ent     = (const float*)d_in[5];
    const float* rel     = (const float*)d_in[6];
    const float* W       = (const float*)d_in[7];
    const float* bias    = (const float*)d_in[8];
    float* out = (float*)d_out;

    const int B = in_sizes[0];   // 8192

    static bool attr_set = false;
    if (!attr_set) {
        cudaFuncSetAttribute(gemm_kernel,
                             cudaFuncAttributeMaxDynamicSharedMemorySize,
                             SMEM_BYTES);
        attr_set = true;
    }

    dim3 g1((B + 7) / 8);                    // 1024 blocks, 1 warp/item
    gather_kernel<<<g1, 256>>>(u, v, adj_ent, adj_rel, usr, ent, rel, B);

    dim3 g2((B + MBLK - 1) / MBLK);          // 128 blocks -> ONE wave
    gemm_kernel<<<g2, GTHREADS, SMEM_BYTES>>>(u, usr, W, bias, out, B);
}

// round 10
// speedup vs baseline: 1.0156x; 1.0156x over previous
#include <cuda_runtime.h>
#include <cuda_bf16.h>
#include <cstdint>

#define D            128
#define S            16
#define BMAX         8192

// ---------------- scratch (device globals: allocation-free) ----------------
__device__ uint32_t g_x0 [BMAX * D];   // msg + rep0, tf32 bits (GEMM A input)
__device__ float    g_msg[BMAX * D];   // msg fp32 (residual adds)

__device__ __forceinline__ uint32_t f2tf32(float f) {
    uint32_t r;
    asm("cvt.rna.tf32.f32 %0, %1;" : "=r"(r) : "f"(f));
    return r;
}

// ============================ kernel 1: gather =============================
// One warp per item. No smem. 32 warps/SM -> deep gather MLP (~HBM roofline).
__global__ __launch_bounds__(256, 4)
void gather_kernel(const int* __restrict__ u,
                   const int* __restrict__ v,
                   const int* __restrict__ adj_ent,
                   const int* __restrict__ adj_rel,
                   const float* __restrict__ usr,
                   const float* __restrict__ ent,
                   const float* __restrict__ rel,
                   int B)
{
    const int lane = threadIdx.x & 31;
    const int item = blockIdx.x * 8 + (threadIdx.x >> 5);
    if (item >= B) return;

    const float4* usr4 = (const float4*)usr;
    const float4* ent4 = (const float4*)ent;
    const float4* rel4 = (const float4*)rel;
    const int4*   adjE4 = (const int4*)adj_ent;
    const int4*   adjR4 = (const int4*)adj_rel;

    const int iu = u[item];
    const int iv = v[item];

    const float4 uex = usr4[(size_t)iu * 32 + lane];
    const float4 rp  = ent4[(size_t)iv * 32 + lane];

    int eix[S], rix[S];
    #pragma unroll
    for (int q = 0; q < 4; q++) {
        const int4 e = __ldg(&adjE4[iv * 4 + q]);
        const int4 r = __ldg(&adjR4[iv * 4 + q]);
        eix[q*4+0] = e.x; eix[q*4+1] = e.y; eix[q*4+2] = e.z; eix[q*4+3] = e.w;
        rix[q*4+0] = r.x; rix[q*4+1] = r.y; rix[q*4+2] = r.z; rix[q*4+3] = r.w;
    }

    // fused single-pass attention (scores tiny; no-max-sub exp validated)
    float sum = 0.f;
    float4 msg = make_float4(0.f, 0.f, 0.f, 0.f);
    #pragma unroll
    for (int s = 0; s < S; s++) {
        const float4 r4 = rel4[(size_t)rix[s] * 32 + lane];
        const float4 e4 = ent4[(size_t)eix[s] * 32 + lane];
        float p = uex.x * r4.x + uex.y * r4.y + uex.z * r4.z + uex.w * r4.w;
        #pragma unroll
        for (int o = 16; o > 0; o >>= 1)
            p += __shfl_xor_sync(0xffffffffu, p, o);
        const float es = __expf(p);
        sum += es;
        msg.x = fmaf(es, e4.x, msg.x);
        msg.y = fmaf(es, e4.y, msg.y);
        msg.z = fmaf(es, e4.z, msg.z);
        msg.w = fmaf(es, e4.w, msg.w);
    }
    const float inv = __frcp_rn(sum);
    msg.x *= inv; msg.y *= inv; msg.z *= inv; msg.w *= inv;

    ((float4*)(g_msg + item * D))[lane] = msg;
    ((uint4*)(g_x0 + item * D))[lane] =
        make_uint4(f2tf32(msg.x + rp.x), f2tf32(msg.y + rp.y),
                   f2tf32(msg.z + rp.z), f2tf32(msg.w + rp.w));
}

// ============================ kernel 2: GEMM v3 ============================
// 512 threads (16 warps), MBLK=64, grid=128 -> one wave, 4 warps/scheduler.
// Warp tile: M=64 x N=8. B-fragments and msg-fragments register-resident.
// smem: X tile only (64 x 132 tf32 words = 33.8 KB).
#define MBLK         64
#define GTHREADS     512
#define GWARPS       16
#define XSTRIDE      132
#define X_WORDS      (MBLK * XSTRIDE)
#define SMEM_BYTES   (X_WORDS * 4)     // 33792 B

__device__ __forceinline__ void mma_tf32(float acc[4], const uint32_t a[4],
                                         const uint32_t b[2]) {
    asm("mma.sync.aligned.m16n8k8.row.col.f32.tf32.tf32.f32 "
        "{%0,%1,%2,%3}, {%4,%5,%6,%7}, {%8,%9}, {%0,%1,%2,%3};"
        : "+f"(acc[0]), "+f"(acc[1]), "+f"(acc[2]), "+f"(acc[3])
        : "r"(a[0]), "r"(a[1]), "r"(a[2]), "r"(a[3]),
          "r"(b[0]), "r"(b[1]));
}

__global__ __launch_bounds__(GTHREADS, 1)
void gemm_kernel(const int* __restrict__ u,
                 const float* __restrict__ usr,
                 const float* __restrict__ W,
                 const float* __restrict__ bias,
                 float* __restrict__ out,
                 int B)
{
    extern __shared__ uint32_t Xsh[];   // [64][132] tf32 (reused fp32 for h2)

    const int tid  = threadIdx.x;
    const int lane = tid & 31;
    const int wid  = tid >> 5;
    const int g    = lane >> 2;
    const int tq   = lane & 3;

    const int base  = blockIdx.x * MBLK;
    const int ncol0 = wid * 8;          // warp owns N cols [ncol0, ncol0+8)

    // ---- stage X (tf32 from scratch) into smem: 4 rows per warp ----
    #pragma unroll
    for (int r = 0; r < MBLK / GWARPS; r++) {
        const int row = wid * (MBLK / GWARPS) + r;
        const int cit = min(base + row, B - 1);
        ((uint4*)(Xsh + row * XSTRIDE))[lane] = ((const uint4*)(g_x0 + cit * D))[lane];
    }

    // ---- register-resident B fragments: whole K for this warp's 8 cols ----
    uint32_t bf[16][2];
    #pragma unroll
    for (int kt = 0; kt < 16; kt++) {
        bf[kt][0] = f2tf32(__ldg(&W[(kt * 8 + tq)     * D + ncol0 + g]));
        bf[kt][1] = f2tf32(__ldg(&W[(kt * 8 + tq + 4) * D + ncol0 + g]));
    }

    // bias fragment (cols ncol0 + 2tq, +1)
    const float bb0 = __ldg(&bias[ncol0 + tq * 2]);
    const float bb1 = __ldg(&bias[ncol0 + tq * 2 + 1]);

    // msg fragments (same layout as acc): rows mt*16+g / +8, cols ncol0+2tq..+1
    float mf[4][4];
    #pragma unroll
    for (int mt = 0; mt < 4; mt++) {
        const int r0 = min(base + mt * 16 + g,     B - 1);
        const int r1 = min(base + mt * 16 + g + 8, B - 1);
        const float2 m0 = *(const float2*)(g_msg + r0 * D + ncol0 + tq * 2);
        const float2 m1 = *(const float2*)(g_msg + r1 * D + ncol0 + tq * 2);
        mf[mt][0] = m0.x; mf[mt][1] = m0.y;
        mf[mt][2] = m1.x; mf[mt][3] = m1.y;
    }

    __syncthreads();

    float acc[4][4];

    #pragma unroll
    for (int iter = 0; iter < 2; iter++) {
        #pragma unroll
        for (int mt = 0; mt < 4; mt++) {
            acc[mt][0] = bb0; acc[mt][1] = bb1;
            acc[mt][2] = bb0; acc[mt][3] = bb1;
        }

        #pragma unroll
        for (int kt = 0; kt < 16; kt++) {
            #pragma unroll
            for (int mt = 0; mt < 4; mt++) {
                uint32_t a[4];
                const uint32_t* xb = Xsh + (mt * 16 + g) * XSTRIDE + kt * 8 + tq;
                a[0] = xb[0];
                a[1] = xb[8 * XSTRIDE];
                a[2] = xb[4];
                a[3] = xb[8 * XSTRIDE + 4];
                mma_tf32(acc[mt], a, bf[kt]);
            }
        }

        __syncthreads();   // all A reads done before Xsh overwrite

        if (iter == 0) {
            // x1 = msg + relu(h1): warp writes its own 8 cols for all 64 rows
            #pragma unroll
            for (int mt = 0; mt < 4; mt++) {
                const int c0 = ncol0 + tq * 2;
                const int r0 = mt * 16 + g;
                const int r1 = r0 + 8;
                Xsh[r0 * XSTRIDE + c0    ] = f2tf32(mf[mt][0] + fmaxf(acc[mt][0], 0.f));
                Xsh[r0 * XSTRIDE + c0 + 1] = f2tf32(mf[mt][1] + fmaxf(acc[mt][1], 0.f));
                Xsh[r1 * XSTRIDE + c0    ] = f2tf32(mf[mt][2] + fmaxf(acc[mt][2], 0.f));
                Xsh[r1 * XSTRIDE + c0 + 1] = f2tf32(mf[mt][3] + fmaxf(acc[mt][3], 0.f));
            }
            __syncthreads();
        }
    }

    // rep2 = relu(h2) -> Xsh (as f32 bits; Xsh no longer needed as tf32)
    #pragma unroll
    for (int mt = 0; mt < 4; mt++) {
        const int c0 = ncol0 + tq * 2;
        const int r0 = mt * 16 + g;
        const int r1 = r0 + 8;
        Xsh[r0 * XSTRIDE + c0    ] = __float_as_uint(fmaxf(acc[mt][0], 0.f));
        Xsh[r0 * XSTRIDE + c0 + 1] = __float_as_uint(fmaxf(acc[mt][1], 0.f));
        Xsh[r1 * XSTRIDE + c0    ] = __float_as_uint(fmaxf(acc[mt][2], 0.f));
        Xsh[r1 * XSTRIDE + c0 + 1] = __float_as_uint(fmaxf(acc[mt][3], 0.f));
    }
    __syncthreads();

    // ---- epilogue: sigmoid(dot(u_emb, rep2)); 4 rows per warp ----
    const float4* usr4 = (const float4*)usr;
    #pragma unroll
    for (int r = 0; r < MBLK / GWARPS; r++) {
        const int row  = wid * (MBLK / GWARPS) + r;
        const int item = base + row;
        const int cit  = min(item, B - 1);
        const int iu = u[cit];
        const float4 uex = usr4[(size_t)iu * 32 + lane];   // L2-hot from kernel 1
        const float4 h = ((const float4*)(Xsh + row * XSTRIDE))[lane];
        float p = uex.x * h.x + uex.y * h.y + uex.z * h.z + uex.w * h.w;
        #pragma unroll
        for (int o = 16; o > 0; o >>= 1)
            p += __shfl_xor_sync(0xffffffffu, p, o);
        if (lane == 0 && item < B)
            out[item] = 1.f / (1.f + __expf(-p));
    }
}

// ================================ launch ===================================
extern "C" void kernel_launch(void* const* d_in, const int* in_sizes, int n_in,
                              void* d_out, int out_size)
{
    const int*   u       = (const int*)d_in[0];
    const int*   v       = (const int*)d_in[1];
    const int*   adj_ent = (const int*)d_in[2];
    const int*   adj_rel = (const int*)d_in[3];
    const float* usr     = (const float*)d_in[4];
    const float* ent     = (const float*)d_in[5];
    const float* rel     = (const float*)d_in[6];
    const float* W       = (const float*)d_in[7];
    const float* bias    = (const float*)d_in[8];
    float* out = (float*)d_out;

    const int B = in_sizes[0];   // 8192

    dim3 g1((B + 7) / 8);                    // 1024 blocks, 1 warp/item
    gather_kernel<<<g1, 256>>>(u, v, adj_ent, adj_rel, usr, ent, rel, B);

    dim3 g2((B + MBLK - 1) / MBLK);          // 128 blocks -> one wave
    gemm_kernel<<<g2, GTHREADS, SMEM_BYTES>>>(u, usr, W, bias, out, B);
}

// round 11
// speedup vs baseline: 1.1651x; 1.1472x over previous
#include <cuda_runtime.h>
#include <cuda_bf16.h>
#include <cstdint>

#define D            128
#define S            16
#define WARPS_PB     8
#define ITEM_TILE    4
#define ITEMS_PB     32
#define BLOCK_THREADS 256

// smem layout (bytes):
//   Wt  bf16 [128 n][136 k-stride]  = 34816   (reused as Hs fp32 [32][132] later)
//   Xs  bf16 [32 rows][136 k]       = 8704
//   Ms  bf16 [32 rows][136 k]       = 8704
#define WT_BYTES     34816
#define XS_BYTES     8704
#define SMEM_BYTES   (WT_BYTES + 2 * XS_BYTES)   // 52224 -> 3 blocks/SM (156KB)

#define HSTRIDE      136    // halfword stride for Wt/Xs/Ms
#define FSTRIDE      132    // float stride for Hs

__device__ __forceinline__ void mma_bf16(float acc[4], const uint32_t a[4],
                                         const uint32_t b[2]) {
    asm("mma.sync.aligned.m16n8k16.row.col.f32.bf16.bf16.f32 "
        "{%0,%1,%2,%3}, {%4,%5,%6,%7}, {%8,%9}, {%0,%1,%2,%3};"
        : "+f"(acc[0]), "+f"(acc[1]), "+f"(acc[2]), "+f"(acc[3])
        : "r"(a[0]), "r"(a[1]), "r"(a[2]), "r"(a[3]),
          "r"(b[0]), "r"(b[1]));
}

__device__ __forceinline__ uint32_t pack_bf16x2(float lo, float hi) {
    __nv_bfloat162 v = __floats2bfloat162_rn(lo, hi);
    return *(uint32_t*)&v;
}

__global__ __launch_bounds__(BLOCK_THREADS, 3)     // 24 warps/SM
void kgcn_kernel(const int* __restrict__ u,
                 const int* __restrict__ v,
                 const int* __restrict__ adj_ent,
                 const int* __restrict__ adj_rel,
                 const float* __restrict__ usr,
                 const float* __restrict__ ent,
                 const float* __restrict__ rel,
                 const float* __restrict__ W,
                 const float* __restrict__ bias,
                 float* __restrict__ out,
                 int B)
{
    extern __shared__ char sm[];
    __nv_bfloat16* Wt = (__nv_bfloat16*)sm;                  // [n][k] transposed
    __nv_bfloat16* Xs = (__nv_bfloat16*)(sm + WT_BYTES);
    __nv_bfloat16* Ms = (__nv_bfloat16*)(sm + WT_BYTES + XS_BYTES);
    float*         Hs = (float*)sm;                          // reuses Wt region

    const int tid  = threadIdx.x;
    const int lane = tid & 31;
    const int wid  = tid >> 5;
    const int g    = lane >> 2;
    const int tq   = lane & 3;

    // ---- stage W transposed -> bf16 smem: Wt[n][k] = W[k][n] ----
    for (int idx = tid; idx < D * D; idx += BLOCK_THREADS) {
        const int k = idx >> 7;
        const int n = idx & 127;
        Wt[n * HSTRIDE + k] = __float2bfloat16(W[idx]);
    }

    const int base = (blockIdx.x * WARPS_PB + wid) * ITEM_TILE;

    const float4* usr4 = (const float4*)usr;
    const float4* ent4 = (const float4*)ent;
    const float4* rel4 = (const float4*)rel;
    const int4*   adjE4 = (const int4*)adj_ent;
    const int4*   adjR4 = (const int4*)adj_rel;

    // ================= gather + attention (per-warp, 4 items) ==============
    #pragma unroll
    for (int t = 0; t < ITEM_TILE; t++) {
        const int item = base + t;
        const int cit  = item < B ? item : (B - 1);
        const int iu = u[cit];
        const int iv = v[cit];

        const float4 uex = usr4[(size_t)iu * 32 + lane];
        const float4 rp  = ent4[(size_t)iv * 32 + lane];

        // fused single-pass attention in groups of 4 neighbors (reg-friendly)
        float sum = 0.f;
        float4 msg = make_float4(0.f, 0.f, 0.f, 0.f);
        #pragma unroll
        for (int q = 0; q < 4; q++) {
            const int4 ei = __ldg(&adjE4[iv * 4 + q]);
            const int4 ri = __ldg(&adjR4[iv * 4 + q]);
            const int es[4] = {ei.x, ei.y, ei.z, ei.w};
            const int rs[4] = {ri.x, ri.y, ri.z, ri.w};
            #pragma unroll
            for (int s = 0; s < 4; s++) {
                const float4 r4 = rel4[(size_t)rs[s] * 32 + lane];
                const float4 e4 = ent4[(size_t)es[s] * 32 + lane];
                float p = uex.x * r4.x + uex.y * r4.y + uex.z * r4.z + uex.w * r4.w;
                #pragma unroll
                for (int o = 16; o > 0; o >>= 1)
                    p += __shfl_xor_sync(0xffffffffu, p, o);
                const float e = __expf(p);   // |p| << 1: no-max-sub validated
                sum += e;
                msg.x = fmaf(e, e4.x, msg.x);
                msg.y = fmaf(e, e4.y, msg.y);
                msg.z = fmaf(e, e4.z, msg.z);
                msg.w = fmaf(e, e4.w, msg.w);
            }
        }
        const float inv = __frcp_rn(sum);
        msg.x *= inv; msg.y *= inv; msg.z *= inv; msg.w *= inv;

        // store msg (bf16) and x0 = msg + rep0 (bf16) to smem
        const int row = wid * ITEM_TILE + t;
        uint32_t* xp = (uint32_t*)(Xs + row * HSTRIDE + lane * 4);
        uint32_t* mp = (uint32_t*)(Ms + row * HSTRIDE + lane * 4);
        xp[0] = pack_bf16x2(msg.x + rp.x, msg.y + rp.y);
        xp[1] = pack_bf16x2(msg.z + rp.z, msg.w + rp.w);
        mp[0] = pack_bf16x2(msg.x, msg.y);
        mp[1] = pack_bf16x2(msg.z, msg.w);
    }
    __syncthreads();

    // ================= GEMM: 2 layers of relu(x @ W + b) ====================
    // block M=32, N=128, K=128; warp owns 16 N-cols (nt=2), mt=2, kt=8 (K=16/mma)
    const int ncol0 = wid * 16;
    float bb[2][2];
    #pragma unroll
    for (int nt = 0; nt < 2; nt++) {
        bb[nt][0] = __ldg(&bias[ncol0 + nt * 8 + tq * 2]);
        bb[nt][1] = __ldg(&bias[ncol0 + nt * 8 + tq * 2 + 1]);
    }

    float acc[2][2][4];

    #pragma unroll
    for (int iter = 0; iter < 2; iter++) {
        #pragma unroll
        for (int mt = 0; mt < 2; mt++)
            #pragma unroll
            for (int nt = 0; nt < 2; nt++) {
                acc[mt][nt][0] = bb[nt][0]; acc[mt][nt][1] = bb[nt][1];
                acc[mt][nt][2] = bb[nt][0]; acc[mt][nt][3] = bb[nt][1];
            }

        #pragma unroll
        for (int kt = 0; kt < 8; kt++) {
            uint32_t a[2][4];
            #pragma unroll
            for (int mt = 0; mt < 2; mt++) {
                const __nv_bfloat16* xb = Xs + (mt * 16 + g) * HSTRIDE + kt * 16 + tq * 2;
                a[mt][0] = *(const uint32_t*)(xb);
                a[mt][1] = *(const uint32_t*)(xb + 8 * HSTRIDE);
                a[mt][2] = *(const uint32_t*)(xb + 8);
                a[mt][3] = *(const uint32_t*)(xb + 8 * HSTRIDE + 8);
            }
            uint32_t b[2][2];
            #pragma unroll
            for (int nt = 0; nt < 2; nt++) {
                const __nv_bfloat16* wb = Wt + (ncol0 + nt * 8 + g) * HSTRIDE + kt * 16 + tq * 2;
                b[nt][0] = *(const uint32_t*)(wb);
                b[nt][1] = *(const uint32_t*)(wb + 8);
            }
            #pragma unroll
            for (int mt = 0; mt < 2; mt++)
                #pragma unroll
                for (int nt = 0; nt < 2; nt++)
                    mma_bf16(acc[mt][nt], a[mt], b[nt]);
        }

        __syncthreads();   // all Xs (and final Wt) reads complete

        if (iter == 0) {
            // x1 = msg + relu(h1): warp writes its own 16 cols for all 32 rows
            #pragma unroll
            for (int mt = 0; mt < 2; mt++) {
                #pragma unroll
                for (int nt = 0; nt < 2; nt++) {
                    const int c0 = ncol0 + nt * 8 + tq * 2;
                    const int r0 = mt * 16 + g;
                    const int r1 = r0 + 8;
                    const float2 m0 = __bfloat1622float2(*(const __nv_bfloat162*)(Ms + r0 * HSTRIDE + c0));
                    const float2 m1 = __bfloat1622float2(*(const __nv_bfloat162*)(Ms + r1 * HSTRIDE + c0));
                    *(uint32_t*)(Xs + r0 * HSTRIDE + c0) =
                        pack_bf16x2(m0.x + fmaxf(acc[mt][nt][0], 0.f),
                                    m0.y + fmaxf(acc[mt][nt][1], 0.f));
                    *(uint32_t*)(Xs + r1 * HSTRIDE + c0) =
                        pack_bf16x2(m1.x + fmaxf(acc[mt][nt][2], 0.f),
                                    m1.y + fmaxf(acc[mt][nt][3], 0.f));
                }
            }
            __syncthreads();
        }
    }

    // rep2 = relu(h2) -> Hs fp32 (reuses Wt region; Wt reads are done)
    #pragma unroll
    for (int mt = 0; mt < 2; mt++) {
        #pragma unroll
        for (int nt = 0; nt < 2; nt++) {
            const int c0 = ncol0 + nt * 8 + tq * 2;
            const int r0 = mt * 16 + g;
            const int r1 = r0 + 8;
            *(float2*)(Hs + r0 * FSTRIDE + c0) =
                make_float2(fmaxf(acc[mt][nt][0], 0.f), fmaxf(acc[mt][nt][1], 0.f));
            *(float2*)(Hs + r1 * FSTRIDE + c0) =
                make_float2(fmaxf(acc[mt][nt][2], 0.f), fmaxf(acc[mt][nt][3], 0.f));
        }
    }
    __syncthreads();

    // ================= epilogue: sigmoid(dot(u_emb, rep2)) =================
    #pragma unroll
    for (int t = 0; t < ITEM_TILE; t++) {
        const int item = base + t;
        const int cit  = item < B ? item : (B - 1);
        const int iu = u[cit];
        const float4 uex = usr4[(size_t)iu * 32 + lane];   // L2-hot reload
        const int row = wid * ITEM_TILE + t;
        const float4 h = *(const float4*)(Hs + row * FSTRIDE + lane * 4);
        float p = uex.x * h.x + uex.y * h.y + uex.z * h.z + uex.w * h.w;
        #pragma unroll
        for (int o = 16; o > 0; o >>= 1)
            p += __shfl_xor_sync(0xffffffffu, p, o);
        if (lane == 0 && item < B)
            out[item] = 1.f / (1.f + __expf(-p));
    }
}

extern "C" void kernel_launch(void* const* d_in, const int* in_sizes, int n_in,
                              void* d_out, int out_size)
{
    const int*   u       = (const int*)d_in[0];
    const int*   v       = (const int*)d_in[1];
    const int*   adj_ent = (const int*)d_in[2];
    const int*   adj_rel = (const int*)d_in[3];
    const float* usr     = (const float*)d_in[4];
    const float* ent     = (const float*)d_in[5];
    const float* rel     = (const float*)d_in[6];
    const float* W       = (const float*)d_in[7];
    const float* bias    = (const float*)d_in[8];
    float* out = (float*)d_out;

    const int B = in_sizes[0];

    static bool attr_set = false;
    if (!attr_set) {
        cudaFuncSetAttribute(kgcn_kernel,
                             cudaFuncAttributeMaxDynamicSharedMemorySize,
                             SMEM_BYTES);
        attr_set = true;
    }

    dim3 grid((B + ITEMS_PB - 1) / ITEMS_PB);   // 256 blocks, 3/SM co-resident
    kgcn_kernel<<<grid, BLOCK_THREADS, SMEM_BYTES>>>(
        u, v, adj_ent, adj_rel, usr, ent, rel, W, bias, out, B);
}

// round 12
// speedup vs baseline: 1.2293x; 1.0552x over previous
#include <cuda_runtime.h>
#include <cuda_bf16.h>
#include <cstdint>

#define D            128
#define S            16
#define WARPS_PB     16
#define ITEM_TILE    2
#define ITEMS_PB     32
#define BLOCK_THREADS 512

// smem layout (bytes):
//   Wt  bf16 [128 n][136 k-stride]  = 34816  (reused as Hs fp32 [32][132])
//   Xs  bf16 [32 rows][136 k]       = 8704
//   Ms  bf16 [32 rows][136 k]       = 8704
#define WT_BYTES     34816
#define XS_BYTES     8704
#define SMEM_BYTES   (WT_BYTES + 2 * XS_BYTES)   // 52224 -> 2 blocks/SM = 32 warps
#define HSTRIDE      136
#define FSTRIDE      132

__device__ __forceinline__ void mma_bf16(float acc[4], const uint32_t a[4],
                                         const uint32_t b[2]) {
    asm("mma.sync.aligned.m16n8k16.row.col.f32.bf16.bf16.f32 "
        "{%0,%1,%2,%3}, {%4,%5,%6,%7}, {%8,%9}, {%0,%1,%2,%3};"
        : "+f"(acc[0]), "+f"(acc[1]), "+f"(acc[2]), "+f"(acc[3])
        : "r"(a[0]), "r"(a[1]), "r"(a[2]), "r"(a[3]),
          "r"(b[0]), "r"(b[1]));
}

__device__ __forceinline__ uint32_t pack_bf16x2(float lo, float hi) {
    __nv_bfloat162 v = __floats2bfloat162_rn(lo, hi);
    return *(uint32_t*)&v;
}

__global__ __launch_bounds__(BLOCK_THREADS, 2)     // forces <=64 regs, 32 warps/SM
void kgcn_kernel(const int* __restrict__ u,
                 const int* __restrict__ v,
                 const int* __restrict__ adj_ent,
                 const int* __restrict__ adj_rel,
                 const float* __restrict__ usr,
                 const float* __restrict__ ent,
                 const float* __restrict__ rel,
                 const float* __restrict__ W,
                 const float* __restrict__ bias,
                 float* __restrict__ out,
                 int B)
{
    extern __shared__ char sm[];
    __nv_bfloat16* Wt = (__nv_bfloat16*)sm;                  // [n][k] transposed
    __nv_bfloat16* Xs = (__nv_bfloat16*)(sm + WT_BYTES);
    __nv_bfloat16* Ms = (__nv_bfloat16*)(sm + WT_BYTES + XS_BYTES);
    float*         Hs = (float*)sm;                          // reuses Wt region

    const int tid  = threadIdx.x;
    const int lane = tid & 31;
    const int wid  = tid >> 5;
    const int g    = lane >> 2;
    const int tq   = lane & 3;

    // ---- stage W transposed -> bf16 smem: Wt[n][k] = W[k][n] ----
    for (int idx = tid; idx < D * D; idx += BLOCK_THREADS) {
        const int k = idx >> 7;
        const int n = idx & 127;
        Wt[n * HSTRIDE + k] = __float2bfloat16(W[idx]);
    }

    const int base = (blockIdx.x * WARPS_PB + wid) * ITEM_TILE;

    const float4* usr4 = (const float4*)usr;
    const float4* ent4 = (const float4*)ent;
    const float4* rel4 = (const float4*)rel;
    const int4*   adjE4 = (const int4*)adj_ent;
    const int4*   adjR4 = (const int4*)adj_rel;

    // ================= gather + attention (per-warp, 2 items) ==============
    #pragma unroll
    for (int t = 0; t < ITEM_TILE; t++) {
        const int item = base + t;
        const int cit  = item < B ? item : (B - 1);
        const int iu = u[cit];
        const int iv = v[cit];

        const float4 uex = usr4[(size_t)iu * 32 + lane];
        const float4 rp  = ent4[(size_t)iv * 32 + lane];

        // fused single-pass attention, 4 neighbors per index-vector
        float sum = 0.f;
        float4 msg = make_float4(0.f, 0.f, 0.f, 0.f);
        #pragma unroll
        for (int q = 0; q < 4; q++) {
            const int4 ei = __ldg(&adjE4[iv * 4 + q]);
            const int4 ri = __ldg(&adjR4[iv * 4 + q]);
            const int es[4] = {ei.x, ei.y, ei.z, ei.w};
            const int rs[4] = {ri.x, ri.y, ri.z, ri.w};
            #pragma unroll
            for (int s = 0; s < 4; s++) {
                const float4 r4 = rel4[(size_t)rs[s] * 32 + lane];
                const float4 e4 = ent4[(size_t)es[s] * 32 + lane];
                float p = uex.x * r4.x + uex.y * r4.y + uex.z * r4.z + uex.w * r4.w;
                #pragma unroll
                for (int o = 16; o > 0; o >>= 1)
                    p += __shfl_xor_sync(0xffffffffu, p, o);
                const float e = __expf(p);   // |p| << 1: no-max-sub validated
                sum += e;
                msg.x = fmaf(e, e4.x, msg.x);
                msg.y = fmaf(e, e4.y, msg.y);
                msg.z = fmaf(e, e4.z, msg.z);
                msg.w = fmaf(e, e4.w, msg.w);
            }
        }
        const float inv = __frcp_rn(sum);
        msg.x *= inv; msg.y *= inv; msg.z *= inv; msg.w *= inv;

        // store msg (bf16) and x0 = msg + rep0 (bf16)
        const int row = wid * ITEM_TILE + t;
        uint32_t* xp = (uint32_t*)(Xs + row * HSTRIDE + lane * 4);
        uint32_t* mp = (uint32_t*)(Ms + row * HSTRIDE + lane * 4);
        xp[0] = pack_bf16x2(msg.x + rp.x, msg.y + rp.y);
        xp[1] = pack_bf16x2(msg.z + rp.z, msg.w + rp.w);
        mp[0] = pack_bf16x2(msg.x, msg.y);
        mp[1] = pack_bf16x2(msg.z, msg.w);
    }
    __syncthreads();

    // ================= GEMM: 2 layers of relu(x @ W + b) ====================
    // block M=32, N=128, K=128; 16 warps, each owns N=8 cols; mt=2, kt=8
    const int ncol0 = wid * 8;
    const float bb0 = __ldg(&bias[ncol0 + tq * 2]);
    const float bb1 = __ldg(&bias[ncol0 + tq * 2 + 1]);

    float acc[2][4];

    #pragma unroll
    for (int iter = 0; iter < 2; iter++) {
        #pragma unroll
        for (int mt = 0; mt < 2; mt++) {
            acc[mt][0] = bb0; acc[mt][1] = bb1;
            acc[mt][2] = bb0; acc[mt][3] = bb1;
        }

        #pragma unroll
        for (int kt = 0; kt < 8; kt++) {
            uint32_t b[2];
            {
                const __nv_bfloat16* wb = Wt + (ncol0 + g) * HSTRIDE + kt * 16 + tq * 2;
                b[0] = *(const uint32_t*)(wb);
                b[1] = *(const uint32_t*)(wb + 8);
            }
            #pragma unroll
            for (int mt = 0; mt < 2; mt++) {
                uint32_t a[4];
                const __nv_bfloat16* xb = Xs + (mt * 16 + g) * HSTRIDE + kt * 16 + tq * 2;
                a[0] = *(const uint32_t*)(xb);
                a[1] = *(const uint32_t*)(xb + 8 * HSTRIDE);
                a[2] = *(const uint32_t*)(xb + 8);
                a[3] = *(const uint32_t*)(xb + 8 * HSTRIDE + 8);
                mma_bf16(acc[mt], a, b);
            }
        }

        __syncthreads();   // all Xs/Wt reads complete

        if (iter == 0) {
            // x1 = msg + relu(h1): warp writes its own 8 cols for all 32 rows
            #pragma unroll
            for (int mt = 0; mt < 2; mt++) {
                const int c0 = ncol0 + tq * 2;
                const int r0 = mt * 16 + g;
                const int r1 = r0 + 8;
                const float2 m0 = __bfloat1622float2(*(const __nv_bfloat162*)(Ms + r0 * HSTRIDE + c0));
                const float2 m1 = __bfloat1622float2(*(const __nv_bfloat162*)(Ms + r1 * HSTRIDE + c0));
                *(uint32_t*)(Xs + r0 * HSTRIDE + c0) =
                    pack_bf16x2(m0.x + fmaxf(acc[mt][0], 0.f),
                                m0.y + fmaxf(acc[mt][1], 0.f));
                *(uint32_t*)(Xs + r1 * HSTRIDE + c0) =
                    pack_bf16x2(m1.x + fmaxf(acc[mt][2], 0.f),
                                m1.y + fmaxf(acc[mt][3], 0.f));
            }
            __syncthreads();
        }
    }

    // rep2 = relu(h2) -> Hs fp32 (reuses Wt region; Wt reads are done)
    #pragma unroll
    for (int mt = 0; mt < 2; mt++) {
        const int c0 = ncol0 + tq * 2;
        const int r0 = mt * 16 + g;
        const int r1 = r0 + 8;
        *(float2*)(Hs + r0 * FSTRIDE + c0) =
            make_float2(fmaxf(acc[mt][0], 0.f), fmaxf(acc[mt][1], 0.f));
        *(float2*)(Hs + r1 * FSTRIDE + c0) =
            make_float2(fmaxf(acc[mt][2], 0.f), fmaxf(acc[mt][3], 0.f));
    }
    __syncthreads();

    // ================= epilogue: sigmoid(dot(u_emb, rep2)) =================
    #pragma unroll
    for (int t = 0; t < ITEM_TILE; t++) {
        const int item = base + t;
        const int cit  = item < B ? item : (B - 1);
        const int iu = u[cit];
        const float4 uex = usr4[(size_t)iu * 32 + lane];   // L2-hot reload
        const int row = wid * ITEM_TILE + t;
        const float4 h = *(const float4*)(Hs + row * FSTRIDE + lane * 4);
        float p = uex.x * h.x + uex.y * h.y + uex.z * h.z + uex.w * h.w;
        #pragma unroll
        for (int o = 16; o > 0; o >>= 1)
            p += __shfl_xor_sync(0xffffffffu, p, o);
        if (lane == 0 && item < B)
            out[item] = 1.f / (1.f + __expf(-p));
    }
}

extern "C" void kernel_launch(void* const* d_in, const int* in_sizes, int n_in,
                              void* d_out, int out_size)
{
    const int*   u       = (const int*)d_in[0];
    const int*   v       = (const int*)d_in[1];
    const int*   adj_ent = (const int*)d_in[2];
    const int*   adj_rel = (const int*)d_in[3];
    const float* usr     = (const float*)d_in[4];
    const float* ent     = (const float*)d_in[5];
    const float* rel     = (const float*)d_in[6];
    const float* W       = (const float*)d_in[7];
    const float* bias    = (const float*)d_in[8];
    float* out = (float*)d_out;

    const int B = in_sizes[0];

    static bool attr_set = false;
    if (!attr_set) {
        cudaFuncSetAttribute(kgcn_kernel,
                             cudaFuncAttributeMaxDynamicSharedMemorySize,
                             SMEM_BYTES);
        attr_set = true;
    }

    dim3 grid((B + ITEMS_PB - 1) / ITEMS_PB);   // 256 blocks, 2/SM -> 32 warps/SM
    kgcn_kernel<<<grid, BLOCK_THREADS, SMEM_BYTES>>>(
        u, v, adj_ent, adj_rel, usr, ent, rel, W, bias, out, B);
}

// round 13
// speedup vs baseline: 1.2931x; 1.0519x over previous
#include <cuda_runtime.h>
#include <cuda_bf16.h>
#include <cstdint>

#define D            128
#define S            16
#define NREL         64
#define WARPS_PB     16
#define ITEM_TILE    2
#define ITEMS_PB     32
#define BLOCK_THREADS 512

#define HSTRIDE      136    // bf16 stride (Wt/Rt/Xs/Ms/Us)
#define FSTRIDE      132    // fp32 stride (Hs)
#define SCSTRIDE     68     // fp32 stride (SC)

// smem layout (bytes):
//   Wt bf16 [128][136] = 34816   (reused as Hs fp32 [32][132] in epilogue)
//   Rt bf16 [64][136]  = 17408
//   SC fp32 [32][68]   = 8704
//   Xs bf16 [32][136]  = 8704    (first used as Us: U tile for score GEMM)
//   Ms bf16 [32][136]  = 8704
#define OFF_WT  0
#define OFF_RT  34816
#define OFF_SC  (34816 + 17408)
#define OFF_XS  (OFF_SC + 8704)
#define OFF_MS  (OFF_XS + 8704)
#define SMEM_BYTES (OFF_MS + 8704)          // 78336 -> 2 blocks/SM (156.7KB)

__device__ __forceinline__ void mma_bf16(float acc[4], const uint32_t a[4],
                                         const uint32_t b[2]) {
    asm("mma.sync.aligned.m16n8k16.row.col.f32.bf16.bf16.f32 "
        "{%0,%1,%2,%3}, {%4,%5,%6,%7}, {%8,%9}, {%0,%1,%2,%3};"
        : "+f"(acc[0]), "+f"(acc[1]), "+f"(acc[2]), "+f"(acc[3])
        : "r"(a[0]), "r"(a[1]), "r"(a[2]), "r"(a[3]),
          "r"(b[0]), "r"(b[1]));
}

__device__ __forceinline__ uint32_t pack_bf16x2(float lo, float hi) {
    __nv_bfloat162 v = __floats2bfloat162_rn(lo, hi);
    return *(uint32_t*)&v;
}

__global__ __launch_bounds__(BLOCK_THREADS, 2)     // 32 warps/SM
void kgcn_kernel(const int* __restrict__ u,
                 const int* __restrict__ v,
                 const int* __restrict__ adj_ent,
                 const int* __restrict__ adj_rel,
                 const float* __restrict__ usr,
                 const float* __restrict__ ent,
                 const float* __restrict__ rel,
                 const float* __restrict__ W,
                 const float* __restrict__ bias,
                 float* __restrict__ out,
                 int B)
{
    extern __shared__ char sm[];
    __nv_bfloat16* Wt = (__nv_bfloat16*)(sm + OFF_WT);   // [n][k] transposed W
    __nv_bfloat16* Rt = (__nv_bfloat16*)(sm + OFF_RT);   // [r][k] rel table
    float*         SC = (float*)        (sm + OFF_SC);   // [row][r] scores
    __nv_bfloat16* Xs = (__nv_bfloat16*)(sm + OFF_XS);   // U tile, then X tile
    __nv_bfloat16* Ms = (__nv_bfloat16*)(sm + OFF_MS);   // msg tile
    float*         Hs = (float*)        (sm + OFF_WT);   // epilogue reuse of Wt

    const int tid  = threadIdx.x;
    const int lane = tid & 31;
    const int wid  = tid >> 5;
    const int g    = lane >> 2;
    const int tq   = lane & 3;

    // ---- stage Wt (transposed) and Rt (row-major) as bf16 ----
    for (int idx = tid; idx < D * D; idx += BLOCK_THREADS) {
        const int k = idx >> 7;
        const int n = idx & 127;
        Wt[n * HSTRIDE + k] = __float2bfloat16(W[idx]);
    }
    for (int idx = tid; idx < NREL * D; idx += BLOCK_THREADS) {
        const int r = idx >> 7;
        const int k = idx & 127;
        Rt[r * HSTRIDE + k] = __float2bfloat16(rel[idx]);
    }

    const int base = (blockIdx.x * WARPS_PB + wid) * ITEM_TILE;

    const float4* usr4 = (const float4*)usr;
    const float4* ent4 = (const float4*)ent;
    const int4*   adjE4 = (const int4*)adj_ent;
    const int4*   adjR4 = (const int4*)adj_rel;

    // ---- stage U tile (bf16) into Xs (Us alias) ----
    #pragma unroll
    for (int t = 0; t < ITEM_TILE; t++) {
        const int item = base + t;
        const int cit  = item < B ? item : (B - 1);
        const float4 uex = usr4[(size_t)u[cit] * 32 + lane];
        const int row = wid * ITEM_TILE + t;
        uint32_t* up = (uint32_t*)(Xs + row * HSTRIDE + lane * 4);
        up[0] = pack_bf16x2(uex.x, uex.y);
        up[1] = pack_bf16x2(uex.z, uex.w);
    }
    __syncthreads();

    // ---- score GEMM: SC[32x64] = U[32x128] @ Rt^T, warps 0-7 ----
    if (wid < 8) {
        const int ncol0 = wid * 8;
        float sacc[2][4];
        #pragma unroll
        for (int mt = 0; mt < 2; mt++) {
            sacc[mt][0] = 0.f; sacc[mt][1] = 0.f;
            sacc[mt][2] = 0.f; sacc[mt][3] = 0.f;
        }
        #pragma unroll
        for (int kt = 0; kt < 8; kt++) {
            uint32_t b[2];
            const __nv_bfloat16* rb = Rt + (ncol0 + g) * HSTRIDE + kt * 16 + tq * 2;
            b[0] = *(const uint32_t*)(rb);
            b[1] = *(const uint32_t*)(rb + 8);
            #pragma unroll
            for (int mt = 0; mt < 2; mt++) {
                uint32_t a[4];
                const __nv_bfloat16* xb = Xs + (mt * 16 + g) * HSTRIDE + kt * 16 + tq * 2;
                a[0] = *(const uint32_t*)(xb);
                a[1] = *(const uint32_t*)(xb + 8 * HSTRIDE);
                a[2] = *(const uint32_t*)(xb + 8);
                a[3] = *(const uint32_t*)(xb + 8 * HSTRIDE + 8);
                mma_bf16(sacc[mt], a, b);
            }
        }
        #pragma unroll
        for (int mt = 0; mt < 2; mt++) {
            const int c0 = ncol0 + tq * 2;
            const int r0 = mt * 16 + g;
            const int r1 = r0 + 8;
            *(float2*)(SC + r0 * SCSTRIDE + c0) = make_float2(sacc[mt][0], sacc[mt][1]);
            *(float2*)(SC + r1 * SCSTRIDE + c0) = make_float2(sacc[mt][2], sacc[mt][3]);
        }
    }
    __syncthreads();

    // ================= gather + attention (per-warp, 2 items) ==============
    #pragma unroll
    for (int t = 0; t < ITEM_TILE; t++) {
        const int item = base + t;
        const int cit  = item < B ? item : (B - 1);
        const int iv = v[cit];
        const int row = wid * ITEM_TILE + t;

        const float4 rp = ent4[(size_t)iv * 32 + lane];
        const float* scr = SC + row * SCSTRIDE;

        float sum = 0.f;
        float4 msg = make_float4(0.f, 0.f, 0.f, 0.f);
        #pragma unroll
        for (int q = 0; q < 4; q++) {
            const int4 ei = __ldg(&adjE4[iv * 4 + q]);
            const int4 ri = __ldg(&adjR4[iv * 4 + q]);
            const int es_[4] = {ei.x, ei.y, ei.z, ei.w};
            const int rs_[4] = {ri.x, ri.y, ri.z, ri.w};
            #pragma unroll
            for (int s = 0; s < 4; s++) {
                const float4 e4 = ent4[(size_t)es_[s] * 32 + lane];
                const float p = scr[rs_[s]];          // LDS broadcast
                const float e = __expf(p);            // |p| << 1: no-max-sub OK
                sum += e;
                msg.x = fmaf(e, e4.x, msg.x);
                msg.y = fmaf(e, e4.y, msg.y);
                msg.z = fmaf(e, e4.z, msg.z);
                msg.w = fmaf(e, e4.w, msg.w);
            }
        }
        const float inv = __frcp_rn(sum);
        msg.x *= inv; msg.y *= inv; msg.z *= inv; msg.w *= inv;

        // overwrite Xs (U tile dead) with x0; store msg to Ms
        uint32_t* xp = (uint32_t*)(Xs + row * HSTRIDE + lane * 4);
        uint32_t* mp = (uint32_t*)(Ms + row * HSTRIDE + lane * 4);
        xp[0] = pack_bf16x2(msg.x + rp.x, msg.y + rp.y);
        xp[1] = pack_bf16x2(msg.z + rp.z, msg.w + rp.w);
        mp[0] = pack_bf16x2(msg.x, msg.y);
        mp[1] = pack_bf16x2(msg.z, msg.w);
    }
    __syncthreads();

    // ================= main GEMM: 2 layers relu(x @ W + b) =================
    const int ncol0 = wid * 8;
    const float bb0 = __ldg(&bias[ncol0 + tq * 2]);
    const float bb1 = __ldg(&bias[ncol0 + tq * 2 + 1]);

    float acc[2][4];

    #pragma unroll
    for (int iter = 0; iter < 2; iter++) {
        #pragma unroll
        for (int mt = 0; mt < 2; mt++) {
            acc[mt][0] = bb0; acc[mt][1] = bb1;
            acc[mt][2] = bb0; acc[mt][3] = bb1;
        }

        #pragma unroll
        for (int kt = 0; kt < 8; kt++) {
            uint32_t b[2];
            const __nv_bfloat16* wb = Wt + (ncol0 + g) * HSTRIDE + kt * 16 + tq * 2;
            b[0] = *(const uint32_t*)(wb);
            b[1] = *(const uint32_t*)(wb + 8);
            #pragma unroll
            for (int mt = 0; mt < 2; mt++) {
                uint32_t a[4];
                const __nv_bfloat16* xb = Xs + (mt * 16 + g) * HSTRIDE + kt * 16 + tq * 2;
                a[0] = *(const uint32_t*)(xb);
                a[1] = *(const uint32_t*)(xb + 8 * HSTRIDE);
                a[2] = *(const uint32_t*)(xb + 8);
                a[3] = *(const uint32_t*)(xb + 8 * HSTRIDE + 8);
                mma_bf16(acc[mt], a, b);
            }
        }

        __syncthreads();

        if (iter == 0) {
            #pragma unroll
            for (int mt = 0; mt < 2; mt++) {
                const int c0 = ncol0 + tq * 2;
                const int r0 = mt * 16 + g;
                const int r1 = r0 + 8;
                const float2 m0 = __bfloat1622float2(*(const __nv_bfloat162*)(Ms + r0 * HSTRIDE + c0));
                const float2 m1 = __bfloat1622float2(*(const __nv_bfloat162*)(Ms + r1 * HSTRIDE + c0));
                *(uint32_t*)(Xs + r0 * HSTRIDE + c0) =
                    pack_bf16x2(m0.x + fmaxf(acc[mt][0], 0.f),
                                m0.y + fmaxf(acc[mt][1], 0.f));
                *(uint32_t*)(Xs + r1 * HSTRIDE + c0) =
                    pack_bf16x2(m1.x + fmaxf(acc[mt][2], 0.f),
                                m1.y + fmaxf(acc[mt][3], 0.f));
            }
            __syncthreads();
        }
    }

    // rep2 = relu(h2) -> Hs fp32 (Wt region; Wt reads done)
    #pragma unroll
    for (int mt = 0; mt < 2; mt++) {
        const int c0 = ncol0 + tq * 2;
        const int r0 = mt * 16 + g;
        const int r1 = r0 + 8;
        *(float2*)(Hs + r0 * FSTRIDE + c0) =
            make_float2(fmaxf(acc[mt][0], 0.f), fmaxf(acc[mt][1], 0.f));
        *(float2*)(Hs + r1 * FSTRIDE + c0) =
            make_float2(fmaxf(acc[mt][2], 0.f), fmaxf(acc[mt][3], 0.f));
    }
    __syncthreads();

    // ================= epilogue: sigmoid(dot(u_emb, rep2)) =================
    #pragma unroll
    for (int t = 0; t < ITEM_TILE; t++) {
        const int item = base + t;
        const int cit  = item < B ? item : (B - 1);
        const float4 uex = usr4[(size_t)u[cit] * 32 + lane];   // L2-hot
        const int row = wid * ITEM_TILE + t;
        const float4 h = *(const float4*)(Hs + row * FSTRIDE + lane * 4);
        float p = uex.x * h.x + uex.y * h.y + uex.z * h.z + uex.w * h.w;
        #pragma unroll
        for (int o = 16; o > 0; o >>= 1)
            p += __shfl_xor_sync(0xffffffffu, p, o);
        if (lane == 0 && item < B)
            out[item] = 1.f / (1.f + __expf(-p));
    }
}

extern "C" void kernel_launch(void* const* d_in, const int* in_sizes, int n_in,
                              void* d_out, int out_size)
{
    const int*   u       = (const int*)d_in[0];
    const int*   v       = (const int*)d_in[1];
    const int*   adj_ent = (const int*)d_in[2];
    const int*   adj_rel = (const int*)d_in[3];
    const float* usr     = (const float*)d_in[4];
    const float* ent     = (const float*)d_in[5];
    const float* rel     = (const float*)d_in[6];
    const float* W       = (const float*)d_in[7];
    const float* bias    = (const float*)d_in[8];
    float* out = (float*)d_out;

    const int B = in_sizes[0];

    static bool attr_set = false;
    if (!attr_set) {
        cudaFuncSetAttribute(kgcn_kernel,
                             cudaFuncAttributeMaxDynamicSharedMemorySize,
                             SMEM_BYTES);
        attr_set = true;
    }

    dim3 grid((B + ITEMS_PB - 1) / ITEMS_PB);   // 256 blocks, 2/SM, 32 warps/SM
    kgcn_kernel<<<grid, BLOCK_THREADS, SMEM_BYTES>>>(
        u, v, adj_ent, adj_rel, usr, ent, rel, W, bias, out, B);
}